// round 12
// baseline (speedup 1.0000x reference)
#include <cuda_runtime.h>
#include <math.h>

#define BSZ   1024
#define NB    30
#define KNN   10
#define HID   128
#define EMB   64
#define NROWS (BSZ*NB)
#define RMSG  128         // rows per k_msg block
#define NTH   512         // k_msg threads
#define PK    132         // operand pitch: bank-conflict-free A frags
#define PB    136         // weight pitch : bank-conflict-free B frags

typedef unsigned long long u64;

__device__ __forceinline__ float tanha(float x) {
    float y; asm("tanh.approx.f32 %0, %1;" : "=f"(y) : "f"(x)); return y;
}
__device__ __forceinline__ unsigned tf32r(float x) {
    unsigned r; asm("cvt.rna.tf32.f32 %0, %1;" : "=r"(r) : "f"(x)); return r;
}

#define MMA_TF32(d0,d1,d2,d3,a0,a1,a2,a3,b0,b1) \
    asm volatile("mma.sync.aligned.m16n8k8.row.col.f32.tf32.tf32.f32 " \
        "{%0,%1,%2,%3},{%4,%5,%6,%7},{%8,%9},{%0,%1,%2,%3};" \
        : "+f"(d0),"+f"(d1),"+f"(d2),"+f"(d3) \
        : "r"(a0),"r"(a1),"r"(a2),"r"(a3),"r"(b0),"r"(b1))

// ---------------- device scratch ----------------
__device__ float g_cf[NB*EMB];
__device__ float g_Wcomb[192*256];
__device__ int   g_nbr[NROWS*KNN];
__device__ float g_A[NROWS*HID];
__device__ float g_C[NROWS*HID];

// ---------------- kernel 0: tiny precompute ----------------
__global__ void k_setup(const float* __restrict__ emb_tab,
                        const float* __restrict__ W_emb,
                        const float* __restrict__ b_emb,
                        const float* __restrict__ W_m1)
{
    int tid = blockIdx.x * blockDim.x + threadIdx.x;
    int stride = gridDim.x * blockDim.x;
    for (int idx = tid; idx < NB*EMB; idx += stride) {
        int n = idx / EMB, e = idx - n*EMB;
        int cat = n / (NB/3);
        float s = b_emb[e];
        for (int k = 0; k < EMB; k++)
            s += tanhf(emb_tab[cat*EMB + k]) * W_emb[k*EMB + e];
        g_cf[idx] = tanhf(s);
    }
    for (int idx = tid; idx < 192*256; idx += stride) {
        int k = idx >> 8, c = idx & 255;
        float v;
        if (c < 128) v = W_m1[k*128 + c] - W_m1[(192+k)*128 + c];
        else         v = W_m1[(192+k)*128 + (c-128)];
        g_Wcomb[idx] = v;
    }
}

// ---------------- kernel 1: per-batch KNN ----------------
__global__ void k_knn(const float* __restrict__ state_inp)
{
    __shared__ float px[NB], py[NB];
    int b = blockIdx.x, t = threadIdx.x;
    if (t < NB) { px[t] = state_inp[b*60 + 2*t]; py[t] = state_inp[b*60 + 2*t + 1]; }
    __syncthreads();
    if (t < NB) {
        float bd[KNN]; int bi[KNN];
        #pragma unroll
        for (int k = 0; k < KNN; k++) { bd[k] = 1e30f; bi[k] = 0; }
        float xi = px[t], yi = py[t];
        for (int j = 0; j < NB; j++) {
            if (j == t) continue;
            float dx = px[j] - xi, dy = py[j] - yi;
            float cd = dx*dx + dy*dy;
            int ci = j;
            #pragma unroll
            for (int k = 0; k < KNN; k++) {
                if (cd < bd[k]) {
                    float td = bd[k]; int ti = bi[k];
                    bd[k] = cd; bi[k] = ci; cd = td; ci = ti;
                }
            }
        }
        #pragma unroll
        for (int k = 0; k < KNN; k++) g_nbr[(b*NB + t)*KNN + k] = bi[k];
    }
}

// ---------------- kernel 2: feat MLP + A/C GEMM via mma tf32 (32 rows/block) ----------------
#define FK_PF  196
#define FK_OT  0
#define FK_OF  (32*PK)
#define FK_OB  (FK_OF + 32*FK_PF)
#define FK_SMEM ((FK_OB + 64*PB) * 4)

__global__ __launch_bounds__(256, 2) void k_feat(
    const float* __restrict__ state_inp, const float* __restrict__ tar,
    const float* __restrict__ W_in1, const float* __restrict__ b_in1,
    const float* __restrict__ W_in2, const float* __restrict__ b_in2,
    const float* __restrict__ b_m1)
{
    extern __shared__ float smem[];
    unsigned* s_t = (unsigned*)(smem + FK_OT);
    unsigned* s_f = (unsigned*)(smem + FK_OF);
    unsigned* s_B = (unsigned*)(smem + FK_OB);
    __shared__ float s_in4[32][4];

    const int tid  = threadIdx.x;
    const int wid  = tid >> 5;
    const int lane = tid & 31;
    const int gid  = lane >> 2;
    const int tig  = lane & 3;
    const int row0 = blockIdx.x * 32;

    if (tid < 128) {
        int r = tid >> 2, q = tid & 3;
        int row = row0 + r;
        int b = row / NB, n = row - b*NB;
        float v = (q < 2) ? state_inp[b*60 + 2*n + q] : tanha(tar[row*2 + (q-2)]);
        s_in4[r][q] = v;
    }
    for (int idx = tid; idx < 32*EMB; idx += 256) {
        int r = idx & 31, e = idx >> 5;
        int n = (row0 + r) % NB;
        s_f[r*FK_PF + 128 + e] = tf32r(g_cf[n*EMB + e]);
    }
    __syncthreads();

    {
        const int c  = tid & 127;
        const int rh = tid >> 7;
        float w0 = W_in1[c], w1 = W_in1[128+c], w2 = W_in1[256+c], w3 = W_in1[384+c];
        float bb = b_in1[c];
        #pragma unroll
        for (int m = 0; m < 16; m++) {
            int r = rh*16 + m;
            float4 in = *reinterpret_cast<const float4*>(&s_in4[r][0]);
            s_t[r*PK + c] = tf32r(tanha(bb + w0*in.x + w1*in.y + w2*in.z + w3*in.w));
        }
    }

    {
        float acc[2][2][4];
        #pragma unroll
        for (int mi = 0; mi < 2; mi++)
            #pragma unroll
            for (int ni = 0; ni < 2; ni++)
                #pragma unroll
                for (int q = 0; q < 4; q++) acc[mi][ni][q] = 0.f;

        for (int ch = 0; ch < 2; ch++) {
            __syncthreads();
            for (int i = tid; i < 64*32; i += 256) {
                int kr = i >> 5, c4 = (i & 31) * 4;
                float4 w = *reinterpret_cast<const float4*>(&W_in2[(ch*64 + kr)*128 + c4]);
                uint4 v = make_uint4(tf32r(w.x), tf32r(w.y), tf32r(w.z), tf32r(w.w));
                *reinterpret_cast<uint4*>(&s_B[kr*PB + c4]) = v;
            }
            __syncthreads();
            #pragma unroll
            for (int ks = 0; ks < 8; ks++) {
                int kg = ch*64 + ks*8, k0 = ks*8;
                unsigned a[2][4];
                #pragma unroll
                for (int mi = 0; mi < 2; mi++) {
                    int r = mi*16 + gid;
                    a[mi][0] = s_t[r*PK + kg + tig];
                    a[mi][1] = s_t[(r+8)*PK + kg + tig];
                    a[mi][2] = s_t[r*PK + kg + 4 + tig];
                    a[mi][3] = s_t[(r+8)*PK + kg + 4 + tig];
                }
                #pragma unroll
                for (int ni = 0; ni < 2; ni++) {
                    int col = wid*16 + ni*8 + gid;
                    unsigned b0 = s_B[(k0 + tig)*PB + col];
                    unsigned b1 = s_B[(k0 + 4 + tig)*PB + col];
                    MMA_TF32(acc[0][ni][0], acc[0][ni][1], acc[0][ni][2], acc[0][ni][3],
                             a[0][0], a[0][1], a[0][2], a[0][3], b0, b1);
                    MMA_TF32(acc[1][ni][0], acc[1][ni][1], acc[1][ni][2], acc[1][ni][3],
                             a[1][0], a[1][1], a[1][2], a[1][3], b0, b1);
                }
            }
        }
        #pragma unroll
        for (int mi = 0; mi < 2; mi++)
            #pragma unroll
            for (int ni = 0; ni < 2; ni++)
                #pragma unroll
                for (int q = 0; q < 4; q++) {
                    int row = mi*16 + gid + ((q >= 2) ? 8 : 0);
                    int col = wid*16 + ni*8 + 2*tig + (q & 1);
                    s_f[row*FK_PF + col] = tf32r(tanha(acc[mi][ni][q] + b_in2[col]));
                }
    }

    float* s_stg = (float*)s_t;
    for (int half = 0; half < 2; half++) {
        float acc[2][2][4];
        #pragma unroll
        for (int mi = 0; mi < 2; mi++)
            #pragma unroll
            for (int ni = 0; ni < 2; ni++)
                #pragma unroll
                for (int q = 0; q < 4; q++) acc[mi][ni][q] = 0.f;

        for (int ch = 0; ch < 3; ch++) {
            __syncthreads();
            for (int i = tid; i < 64*32; i += 256) {
                int kr = i >> 5, c4 = (i & 31) * 4;
                float4 w = *reinterpret_cast<const float4*>(&g_Wcomb[(ch*64 + kr)*256 + half*128 + c4]);
                uint4 v = make_uint4(tf32r(w.x), tf32r(w.y), tf32r(w.z), tf32r(w.w));
                *reinterpret_cast<uint4*>(&s_B[kr*PB + c4]) = v;
            }
            __syncthreads();
            #pragma unroll
            for (int ks = 0; ks < 8; ks++) {
                int kg = ch*64 + ks*8, k0 = ks*8;
                unsigned a[2][4];
                #pragma unroll
                for (int mi = 0; mi < 2; mi++) {
                    int r = mi*16 + gid;
                    a[mi][0] = s_f[r*FK_PF + kg + tig];
                    a[mi][1] = s_f[(r+8)*FK_PF + kg + tig];
                    a[mi][2] = s_f[r*FK_PF + kg + 4 + tig];
                    a[mi][3] = s_f[(r+8)*FK_PF + kg + 4 + tig];
                }
                #pragma unroll
                for (int ni = 0; ni < 2; ni++) {
                    int col = wid*16 + ni*8 + gid;
                    unsigned b0 = s_B[(k0 + tig)*PB + col];
                    unsigned b1 = s_B[(k0 + 4 + tig)*PB + col];
                    MMA_TF32(acc[0][ni][0], acc[0][ni][1], acc[0][ni][2], acc[0][ni][3],
                             a[0][0], a[0][1], a[0][2], a[0][3], b0, b1);
                    MMA_TF32(acc[1][ni][0], acc[1][ni][1], acc[1][ni][2], acc[1][ni][3],
                             a[1][0], a[1][1], a[1][2], a[1][3], b0, b1);
                }
            }
        }
        #pragma unroll
        for (int mi = 0; mi < 2; mi++)
            #pragma unroll
            for (int ni = 0; ni < 2; ni++)
                #pragma unroll
                for (int q = 0; q < 4; q++) {
                    int row = mi*16 + gid + ((q >= 2) ? 8 : 0);
                    int col = wid*16 + ni*8 + 2*tig + (q & 1);
                    float v = acc[mi][ni][q] + (half == 0 ? b_m1[col] : 0.0f);
                    s_stg[row*PK + col] = v;
                }
        __syncthreads();
        float* dst = (half == 0) ? g_C : g_A;
        for (int i = tid; i < 32*32; i += 256) {
            int r = i >> 5, c4 = (i & 31) * 4;
            float4 v = *reinterpret_cast<const float4*>(&s_stg[r*PK + c4]);
            *reinterpret_cast<float4*>(&dst[(row0 + r)*128 + c4]) = v;
        }
    }
}

// ---------------- kernel 3: edge msg via mma tf32, 128 rows, double-buffered ----------------
// dynamic smem (floats):
#define OF_M0  0                         // buf0: 128 x PK
#define OF_M1  (RMSG*PK)                 // buf1: 128 x PK
#define OF_B   (2*RMSG*PK)               // s_B: 128 x PB
#define OF_NB  (OF_B + 128*PB)
#define SMEM_MSG_BYTES ((OF_NB + RMSG*KNN) * 4)

__global__ __launch_bounds__(NTH, 1) void k_msg(
    const float* __restrict__ tar,
    const float* __restrict__ W_m2, const float* __restrict__ b_m2,
    const float* __restrict__ W_a1, const float* __restrict__ b_a1,
    const float* __restrict__ W_a2, const float* __restrict__ b_a2,
    float* __restrict__ out)
{
    extern __shared__ float smem[];
    unsigned* s_buf[2] = { (unsigned*)(smem + OF_M0), (unsigned*)(smem + OF_M1) };
    unsigned* s_B  = (unsigned*)(smem + OF_B);
    int*      s_nb = (int*)(smem + OF_NB);

    const int tid  = threadIdx.x;
    const int wid  = tid >> 5;
    const int lane = tid & 31;
    const int rg   = wid >> 2;          // 0..3 : rows rg*32..+31
    const int cg   = wid & 3;           // 0..3 : cols cg*32..+31
    const int gid  = lane >> 2;
    const int tig  = lane & 3;
    const int row0 = blockIdx.x * RMSG;

    // stage W_m2 + neighbor table
    for (int i = tid; i < 128*32; i += NTH) {
        int k = i >> 5, c4 = (i & 31) * 4;
        float4 w = *reinterpret_cast<const float4*>(&W_m2[k*128 + c4]);
        uint4 v = make_uint4(tf32r(w.x), tf32r(w.y), tf32r(w.z), tf32r(w.w));
        *reinterpret_cast<uint4*>(&s_B[k*PB + c4]) = v;
    }
    for (int idx = tid; idx < RMSG*KNN; idx += NTH) {
        int r = idx / KNN;
        int b = (row0 + r) / NB;
        s_nb[idx] = b*NB + g_nbr[row0*KNN + idx];
    }
    __syncthreads();

    // build(k) into buf[k&1]: m[r][j] = tf32(tanh(C + A_nbr)), 8 float4 per thread
    auto build = [&](int k) {
        unsigned* s_m = s_buf[k & 1];
        #pragma unroll
        for (int it = 0; it < 8; it++) {
            int p = tid + NTH*it;               // 4096 float4 slots
            int r = p >> 5, j = (p & 31) * 4;
            float4 a = *reinterpret_cast<const float4*>(&g_A[s_nb[r*KNN + k]*128 + j]);
            float4 c = *reinterpret_cast<const float4*>(&g_C[(row0 + r)*128 + j]);
            uint4 v = make_uint4(tf32r(tanha(c.x + a.x)), tf32r(tanha(c.y + a.y)),
                                 tf32r(tanha(c.z + a.z)), tf32r(tanha(c.w + a.w)));
            *reinterpret_cast<uint4*>(&s_m[r*PK + j]) = v;
        }
    };

    build(0);
    __syncthreads();

    float vmax[2][4][4];
    #pragma unroll
    for (int mi = 0; mi < 2; mi++)
        #pragma unroll
        for (int ni = 0; ni < 4; ni++)
            #pragma unroll
            for (int q = 0; q < 4; q++) vmax[mi][ni][q] = -1e30f;

    for (int k = 0; k < KNN; k++) {
        // overlap: issue build(k+1) LDGs while GEMM(k) runs
        if (k + 1 < KNN) build(k + 1);

        const unsigned* s_m = s_buf[k & 1];
        float acc[2][4][4];
        #pragma unroll
        for (int mi = 0; mi < 2; mi++)
            #pragma unroll
            for (int ni = 0; ni < 4; ni++)
                #pragma unroll
                for (int q = 0; q < 4; q++) acc[mi][ni][q] = 0.f;

        #pragma unroll
        for (int ks = 0; ks < 16; ks++) {
            int k0 = ks * 8;
            unsigned a[2][4];
            #pragma unroll
            for (int mi = 0; mi < 2; mi++) {
                int r = rg*32 + mi*16 + gid;
                a[mi][0] = s_m[r*PK + k0 + tig];
                a[mi][1] = s_m[(r+8)*PK + k0 + tig];
                a[mi][2] = s_m[r*PK + k0 + 4 + tig];
                a[mi][3] = s_m[(r+8)*PK + k0 + 4 + tig];
            }
            #pragma unroll
            for (int ni = 0; ni < 4; ni++) {
                int col = cg*32 + ni*8 + gid;
                unsigned b0 = s_B[(k0 + tig)*PB + col];
                unsigned b1 = s_B[(k0 + 4 + tig)*PB + col];
                MMA_TF32(acc[0][ni][0], acc[0][ni][1], acc[0][ni][2], acc[0][ni][3],
                         a[0][0], a[0][1], a[0][2], a[0][3], b0, b1);
                MMA_TF32(acc[1][ni][0], acc[1][ni][1], acc[1][ni][2], acc[1][ni][3],
                         a[1][0], a[1][1], a[1][2], a[1][3], b0, b1);
            }
        }
        #pragma unroll
        for (int mi = 0; mi < 2; mi++)
            #pragma unroll
            for (int ni = 0; ni < 4; ni++)
                #pragma unroll
                for (int q = 0; q < 4; q++)
                    vmax[mi][ni][q] = fmaxf(vmax[mi][ni][q], acc[mi][ni][q]);
        __syncthreads();
    }

    // x = tanh(vmax + b_m2) -> buf0 (tf32); stage W_a1
    {
        unsigned* s_x = s_buf[0];
        #pragma unroll
        for (int mi = 0; mi < 2; mi++)
            #pragma unroll
            for (int ni = 0; ni < 4; ni++)
                #pragma unroll
                for (int q = 0; q < 4; q++) {
                    int row = rg*32 + mi*16 + gid + ((q >= 2) ? 8 : 0);
                    int col = cg*32 + ni*8 + 2*tig + (q & 1);
                    float xv = tanha(vmax[mi][ni][q] + b_m2[col]);
                    s_x[row*PK + col] = tf32r(xv);
                }
    }
    for (int i = tid; i < 128*32; i += NTH) {
        int k2 = i >> 5, c4 = (i & 31) * 4;
        float4 w = *reinterpret_cast<const float4*>(&W_a1[k2*128 + c4]);
        uint4 v = make_uint4(tf32r(w.x), tf32r(w.y), tf32r(w.z), tf32r(w.w));
        *reinterpret_cast<uint4*>(&s_B[k2*PB + c4]) = v;
    }
    __syncthreads();

    // y-GEMM from buf0
    {
        const unsigned* s_x = s_buf[0];
        float acc[2][4][4];
        #pragma unroll
        for (int mi = 0; mi < 2; mi++)
            #pragma unroll
            for (int ni = 0; ni < 4; ni++)
                #pragma unroll
                for (int q = 0; q < 4; q++) acc[mi][ni][q] = 0.f;
        #pragma unroll
        for (int ks = 0; ks < 16; ks++) {
            int k0 = ks * 8;
            unsigned a[2][4];
            #pragma unroll
            for (int mi = 0; mi < 2; mi++) {
                int r = rg*32 + mi*16 + gid;
                a[mi][0] = s_x[r*PK + k0 + tig];
                a[mi][1] = s_x[(r+8)*PK + k0 + tig];
                a[mi][2] = s_x[r*PK + k0 + 4 + tig];
                a[mi][3] = s_x[(r+8)*PK + k0 + 4 + tig];
            }
            #pragma unroll
            for (int ni = 0; ni < 4; ni++) {
                int col = cg*32 + ni*8 + gid;
                unsigned b0 = s_B[(k0 + tig)*PB + col];
                unsigned b1 = s_B[(k0 + 4 + tig)*PB + col];
                MMA_TF32(acc[0][ni][0], acc[0][ni][1], acc[0][ni][2], acc[0][ni][3],
                         a[0][0], a[0][1], a[0][2], a[0][3], b0, b1);
                MMA_TF32(acc[1][ni][0], acc[1][ni][1], acc[1][ni][2], acc[1][ni][3],
                         a[1][0], a[1][1], a[1][2], a[1][3], b0, b1);
            }
        }
        __syncthreads();
        // y = tanh(acc + b_a1) -> buf1 (float)
        float* s_y = (float*)s_buf[1];
        #pragma unroll
        for (int mi = 0; mi < 2; mi++)
            #pragma unroll
            for (int ni = 0; ni < 4; ni++)
                #pragma unroll
                for (int q = 0; q < 4; q++) {
                    int row = rg*32 + mi*16 + gid + ((q >= 2) ? 8 : 0);
                    int col = cg*32 + ni*8 + 2*tig + (q & 1);
                    s_y[row*PK + col] = tanha(acc[mi][ni][q] + b_a1[col]);
                }
    }
    __syncthreads();

    // final 128 -> 4, exact squashing (128 rows x 4 outs = 512 threads)
    {
        const float* s_y = (const float*)s_buf[1];
        int r = tid >> 2, o = tid & 3;
        float s = b_a2[o];
        #pragma unroll 4
        for (int kk = 0; kk < 128; kk++) s += s_y[r*PK + kk] * W_a2[kk*4 + o];
        int row = row0 + r;
        int b = row / NB, n = row - b*NB;
        if (o < 2) {
            float tv = tar[row*2 + o];
            out[b*60 + 2*n + o] = 0.3f*tanhf(s) + 0.3f*tanhf(tv);
        } else {
            float t = tanhf(s);
            out[BSZ*60 + b*60 + 2*n + (o-2)] = expf(3.5f*t - 1.5f);
        }
    }
}

// ---------------- launch ----------------
extern "C" void kernel_launch(void* const* d_in, const int* in_sizes, int n_in,
                              void* d_out, int out_size)
{
    const float* state_inp = (const float*)d_in[0];
    const float* tar       = (const float*)d_in[1];
    const float* W_in1     = (const float*)d_in[2];
    const float* b_in1     = (const float*)d_in[3];
    const float* W_in2     = (const float*)d_in[4];
    const float* b_in2     = (const float*)d_in[5];
    const float* emb_tab   = (const float*)d_in[6];
    const float* W_emb     = (const float*)d_in[7];
    const float* b_emb     = (const float*)d_in[8];
    const float* W_m1      = (const float*)d_in[9];
    const float* b_m1      = (const float*)d_in[10];
    const float* W_m2      = (const float*)d_in[11];
    const float* b_m2      = (const float*)d_in[12];
    const float* W_a1      = (const float*)d_in[13];
    const float* b_a1      = (const float*)d_in[14];
    const float* W_a2      = (const float*)d_in[15];
    const float* b_a2      = (const float*)d_in[16];
    float* out = (float*)d_out;

    cudaFuncSetAttribute(k_feat, cudaFuncAttributeMaxDynamicSharedMemorySize, FK_SMEM);
    cudaFuncSetAttribute(k_msg,  cudaFuncAttributeMaxDynamicSharedMemorySize, SMEM_MSG_BYTES);

    k_setup<<<64, 256>>>(emb_tab, W_emb, b_emb, W_m1);
    k_knn<<<BSZ, 32>>>(state_inp);
    k_feat<<<NROWS/32, 256, FK_SMEM>>>(state_inp, tar, W_in1, b_in1, W_in2, b_in2, b_m1);
    k_msg<<<NROWS/RMSG, NTH, SMEM_MSG_BYTES>>>(tar, W_m2, b_m2, W_a1, b_a1, W_a2, b_a2, out);
}

// round 14
// speedup vs baseline: 1.0163x; 1.0163x over previous
#include <cuda_runtime.h>
#include <math.h>

#define BSZ   1024
#define NB    30
#define KNN   10
#define HID   128
#define EMB   64
#define NROWS (BSZ*NB)
#define RMSG  64          // rows per k_msg block
#define PK    132         // operand pitch: bank-conflict-free A frags
#define PB    136         // weight pitch : bank-conflict-free B frags

typedef unsigned long long u64;

__device__ __forceinline__ float tanha(float x) {
    float y; asm("tanh.approx.f32 %0, %1;" : "=f"(y) : "f"(x)); return y;
}
__device__ __forceinline__ unsigned tf32r(float x) {
    unsigned r; asm("cvt.rna.tf32.f32 %0, %1;" : "=r"(r) : "f"(x)); return r;
}

#define MMA_TF32(d0,d1,d2,d3,a0,a1,a2,a3,b0,b1) \
    asm volatile("mma.sync.aligned.m16n8k8.row.col.f32.tf32.tf32.f32 " \
        "{%0,%1,%2,%3},{%4,%5,%6,%7},{%8,%9},{%0,%1,%2,%3};" \
        : "+f"(d0),"+f"(d1),"+f"(d2),"+f"(d3) \
        : "r"(a0),"r"(a1),"r"(a2),"r"(a3),"r"(b0),"r"(b1))

// ---------------- device scratch ----------------
__device__ float g_cf[NB*EMB];
__device__ float g_Wcomb[192*256];
__device__ int   g_nbr[NROWS*KNN];
__device__ float g_A[NROWS*HID];
__device__ float g_C[NROWS*HID];

// ---------------- kernel 0: tiny precompute ----------------
__global__ void k_setup(const float* __restrict__ emb_tab,
                        const float* __restrict__ W_emb,
                        const float* __restrict__ b_emb,
                        const float* __restrict__ W_m1)
{
    int tid = blockIdx.x * blockDim.x + threadIdx.x;
    int stride = gridDim.x * blockDim.x;
    for (int idx = tid; idx < NB*EMB; idx += stride) {
        int n = idx / EMB, e = idx - n*EMB;
        int cat = n / (NB/3);
        float s = b_emb[e];
        for (int k = 0; k < EMB; k++)
            s += tanhf(emb_tab[cat*EMB + k]) * W_emb[k*EMB + e];
        g_cf[idx] = tanhf(s);
    }
    for (int idx = tid; idx < 192*256; idx += stride) {
        int k = idx >> 8, c = idx & 255;
        float v;
        if (c < 128) v = W_m1[k*128 + c] - W_m1[(192+k)*128 + c];
        else         v = W_m1[(192+k)*128 + (c-128)];
        g_Wcomb[idx] = v;
    }
}

// ---------------- kernel 1: per-batch KNN ----------------
__global__ void k_knn(const float* __restrict__ state_inp)
{
    __shared__ float px[NB], py[NB];
    int b = blockIdx.x, t = threadIdx.x;
    if (t < NB) { px[t] = state_inp[b*60 + 2*t]; py[t] = state_inp[b*60 + 2*t + 1]; }
    __syncthreads();
    if (t < NB) {
        float bd[KNN]; int bi[KNN];
        #pragma unroll
        for (int k = 0; k < KNN; k++) { bd[k] = 1e30f; bi[k] = 0; }
        float xi = px[t], yi = py[t];
        for (int j = 0; j < NB; j++) {
            if (j == t) continue;
            float dx = px[j] - xi, dy = py[j] - yi;
            float cd = dx*dx + dy*dy;
            int ci = j;
            #pragma unroll
            for (int k = 0; k < KNN; k++) {
                if (cd < bd[k]) {
                    float td = bd[k]; int ti = bi[k];
                    bd[k] = cd; bi[k] = ci; cd = td; ci = ti;
                }
            }
        }
        #pragma unroll
        for (int k = 0; k < KNN; k++) g_nbr[(b*NB + t)*KNN + k] = bi[k];
    }
}

// ---------------- kernel 2: feat MLP + A/C GEMM via mma tf32 (64 rows/block, 512 thr) ----------------
#define F2R    64
#define FK_PF  196
#define FK_OT  0                          // s_t: 64 x PK
#define FK_OF  (F2R*PK)                   // s_f: 64 x FK_PF
#define FK_OB  (FK_OF + F2R*FK_PF)        // s_B: 64 x PB
#define FK_SMEM ((FK_OB + 64*PB) * 4)

__global__ __launch_bounds__(512, 1) void k_feat(
    const float* __restrict__ state_inp, const float* __restrict__ tar,
    const float* __restrict__ W_in1, const float* __restrict__ b_in1,
    const float* __restrict__ W_in2, const float* __restrict__ b_in2,
    const float* __restrict__ b_m1)
{
    extern __shared__ float smem[];
    unsigned* s_t = (unsigned*)(smem + FK_OT);
    unsigned* s_f = (unsigned*)(smem + FK_OF);
    unsigned* s_B = (unsigned*)(smem + FK_OB);
    __shared__ float s_in4[F2R][4];

    const int tid  = threadIdx.x;
    const int wid  = tid >> 5;          // 16 warps
    const int lane = tid & 31;
    const int gid  = lane >> 2;
    const int tig  = lane & 3;
    const int rg   = wid >> 2;          // 0..3 : rows rg*16..+15
    const int cg   = wid & 3;           // 0..3 : cols cg*32..+31
    const int row0 = blockIdx.x * F2R;

    // inputs + cf
    if (tid < 256) {
        int r = tid >> 2, q = tid & 3;
        int row = row0 + r;
        int b = row / NB, n = row - b*NB;
        float v = (q < 2) ? state_inp[b*60 + 2*n + q] : tanha(tar[row*2 + (q-2)]);
        s_in4[r][q] = v;
    }
    for (int idx = tid; idx < F2R*EMB; idx += 512) {
        int r = idx & (F2R-1), e = idx >> 6;
        int n = (row0 + r) % NB;
        s_f[r*FK_PF + 128 + e] = tf32r(g_cf[n*EMB + e]);
    }
    __syncthreads();

    // stage 1: t = tanh(inp4 @ W_in1 + b_in1) -> s_t tf32 [row][k]
    {
        const int c  = tid & 127;
        const int rh = tid >> 7;        // 0..3 : rows rh*16..+15
        float w0 = W_in1[c], w1 = W_in1[128+c], w2 = W_in1[256+c], w3 = W_in1[384+c];
        float bb = b_in1[c];
        #pragma unroll
        for (int m = 0; m < 16; m++) {
            int r = rh*16 + m;
            float4 in = *reinterpret_cast<const float4*>(&s_in4[r][0]);
            s_t[r*PK + c] = tf32r(tanha(bb + w0*in.x + w1*in.y + w2*in.z + w3*in.w));
        }
    }

    // stage 2: h = t @ W_in2 (2 K-chunks of 64); f = tanh(h + b_in2) -> s_f
    {
        float acc[4][4];
        #pragma unroll
        for (int ni = 0; ni < 4; ni++)
            #pragma unroll
            for (int q = 0; q < 4; q++) acc[ni][q] = 0.f;

        for (int ch = 0; ch < 2; ch++) {
            __syncthreads();
            for (int i = tid; i < 64*32; i += 512) {
                int kr = i >> 5, c4 = (i & 31) * 4;
                float4 w = *reinterpret_cast<const float4*>(&W_in2[(ch*64 + kr)*128 + c4]);
                uint4 v = make_uint4(tf32r(w.x), tf32r(w.y), tf32r(w.z), tf32r(w.w));
                *reinterpret_cast<uint4*>(&s_B[kr*PB + c4]) = v;
            }
            __syncthreads();
            #pragma unroll
            for (int ks = 0; ks < 8; ks++) {
                int kg = ch*64 + ks*8, k0 = ks*8;
                int r = rg*16 + gid;
                unsigned a0 = s_t[r*PK + kg + tig];
                unsigned a1 = s_t[(r+8)*PK + kg + tig];
                unsigned a2 = s_t[r*PK + kg + 4 + tig];
                unsigned a3 = s_t[(r+8)*PK + kg + 4 + tig];
                #pragma unroll
                for (int ni = 0; ni < 4; ni++) {
                    int col = cg*32 + ni*8 + gid;
                    unsigned b0 = s_B[(k0 + tig)*PB + col];
                    unsigned b1 = s_B[(k0 + 4 + tig)*PB + col];
                    MMA_TF32(acc[ni][0], acc[ni][1], acc[ni][2], acc[ni][3],
                             a0, a1, a2, a3, b0, b1);
                }
            }
        }
        __syncthreads();   // all s_B reads done before restaging; s_t reads done
        #pragma unroll
        for (int ni = 0; ni < 4; ni++)
            #pragma unroll
            for (int q = 0; q < 4; q++) {
                int row = rg*16 + gid + ((q >= 2) ? 8 : 0);
                int col = cg*32 + ni*8 + 2*tig + (q & 1);
                s_f[row*FK_PF + col] = tf32r(tanha(acc[ni][q] + b_in2[col]));
            }
    }

    // stage 3: [C|A] = f192 @ Wcomb (2 halves x 3 K-chunks of 64)
    float* s_stg = (float*)s_t;
    for (int half = 0; half < 2; half++) {
        float acc[4][4];
        #pragma unroll
        for (int ni = 0; ni < 4; ni++)
            #pragma unroll
            for (int q = 0; q < 4; q++) acc[ni][q] = 0.f;

        for (int ch = 0; ch < 3; ch++) {
            __syncthreads();
            for (int i = tid; i < 64*32; i += 512) {
                int kr = i >> 5, c4 = (i & 31) * 4;
                float4 w = *reinterpret_cast<const float4*>(&g_Wcomb[(ch*64 + kr)*256 + half*128 + c4]);
                uint4 v = make_uint4(tf32r(w.x), tf32r(w.y), tf32r(w.z), tf32r(w.w));
                *reinterpret_cast<uint4*>(&s_B[kr*PB + c4]) = v;
            }
            __syncthreads();
            #pragma unroll
            for (int ks = 0; ks < 8; ks++) {
                int kg = ch*64 + ks*8, k0 = ks*8;
                int r = rg*16 + gid;
                unsigned a0 = s_f[r*FK_PF + kg + tig];
                unsigned a1 = s_f[(r+8)*FK_PF + kg + tig];
                unsigned a2 = s_f[r*FK_PF + kg + 4 + tig];
                unsigned a3 = s_f[(r+8)*FK_PF + kg + 4 + tig];
                #pragma unroll
                for (int ni = 0; ni < 4; ni++) {
                    int col = cg*32 + ni*8 + gid;
                    unsigned b0 = s_B[(k0 + tig)*PB + col];
                    unsigned b1 = s_B[(k0 + 4 + tig)*PB + col];
                    MMA_TF32(acc[ni][0], acc[ni][1], acc[ni][2], acc[ni][3],
                             a0, a1, a2, a3, b0, b1);
                }
            }
        }
        __syncthreads();   // order acc readout vs s_stg writes (s_t long consumed)
        #pragma unroll
        for (int ni = 0; ni < 4; ni++)
            #pragma unroll
            for (int q = 0; q < 4; q++) {
                int row = rg*16 + gid + ((q >= 2) ? 8 : 0);
                int col = cg*32 + ni*8 + 2*tig + (q & 1);
                s_stg[row*PK + col] = acc[ni][q] + (half == 0 ? b_m1[col] : 0.0f);
            }
        __syncthreads();
        float* dst = (half == 0) ? g_C : g_A;
        for (int i = tid; i < 64*32; i += 512) {
            int r = i >> 5, c4 = (i & 31) * 4;
            float4 v = *reinterpret_cast<const float4*>(&s_stg[r*PK + c4]);
            *reinterpret_cast<float4*>(&dst[(row0 + r)*128 + c4]) = v;
        }
    }
}

// ---------------- kernel 3: edge msg via mma.sync tf32 (R10 version: 64 rows, 256 thr, 2 CTA/SM) ----------------
#define OF_M   0                   // s_m: 64 x PK (tf32 operand / y)
#define OF_B   (64*PK)             // s_B: 128 x PB (tf32 weight)
#define OF_NB  (OF_B + 128*PB)
#define SMEM_MSG_BYTES ((OF_NB + RMSG*KNN) * 4)

__global__ __launch_bounds__(256, 2) void k_msg(
    const float* __restrict__ tar,
    const float* __restrict__ W_m2, const float* __restrict__ b_m2,
    const float* __restrict__ W_a1, const float* __restrict__ b_a1,
    const float* __restrict__ W_a2, const float* __restrict__ b_a2,
    float* __restrict__ out)
{
    extern __shared__ float smem[];
    unsigned* s_m  = (unsigned*)(smem + OF_M);
    unsigned* s_B  = (unsigned*)(smem + OF_B);
    int*      s_nb = (int*)(smem + OF_NB);

    const int tid  = threadIdx.x;
    const int wid  = tid >> 5;
    const int lane = tid & 31;
    const int rg   = wid >> 2;
    const int cg   = wid & 3;
    const int gid  = lane >> 2;
    const int tig  = lane & 3;
    const int row0 = blockIdx.x * RMSG;

    for (int i = tid; i < 128*32; i += 256) {
        int k = i >> 5, c4 = (i & 31) * 4;
        float4 w = *reinterpret_cast<const float4*>(&W_m2[k*128 + c4]);
        uint4 v = make_uint4(tf32r(w.x), tf32r(w.y), tf32r(w.z), tf32r(w.w));
        *reinterpret_cast<uint4*>(&s_B[k*PB + c4]) = v;
    }
    for (int idx = tid; idx < RMSG*KNN; idx += 256) {
        int r = idx / KNN;
        int b = (row0 + r) / NB;
        s_nb[idx] = b*NB + g_nbr[row0*KNN + idx];
    }
    __syncthreads();

    float vmax[2][4][4];
    #pragma unroll
    for (int mi = 0; mi < 2; mi++)
        #pragma unroll
        for (int ni = 0; ni < 4; ni++)
            #pragma unroll
            for (int q = 0; q < 4; q++) vmax[mi][ni][q] = -1e30f;

    for (int k = 0; k < KNN; k++) {
        #pragma unroll
        for (int it = 0; it < 8; it++) {
            int p = tid + 256*it;
            int r = p >> 5, j = (p & 31) * 4;
            float4 a = *reinterpret_cast<const float4*>(&g_A[s_nb[r*KNN + k]*128 + j]);
            float4 c = *reinterpret_cast<const float4*>(&g_C[(row0 + r)*128 + j]);
            uint4 v = make_uint4(tf32r(tanha(c.x + a.x)), tf32r(tanha(c.y + a.y)),
                                 tf32r(tanha(c.z + a.z)), tf32r(tanha(c.w + a.w)));
            *reinterpret_cast<uint4*>(&s_m[r*PK + j]) = v;
        }
        __syncthreads();

        float acc[2][4][4];
        #pragma unroll
        for (int mi = 0; mi < 2; mi++)
            #pragma unroll
            for (int ni = 0; ni < 4; ni++)
                #pragma unroll
                for (int q = 0; q < 4; q++) acc[mi][ni][q] = 0.f;

        #pragma unroll
        for (int ks = 0; ks < 16; ks++) {
            int k0 = ks * 8;
            unsigned a[2][4];
            #pragma unroll
            for (int mi = 0; mi < 2; mi++) {
                int r = rg*32 + mi*16 + gid;
                a[mi][0] = s_m[r*PK + k0 + tig];
                a[mi][1] = s_m[(r+8)*PK + k0 + tig];
                a[mi][2] = s_m[r*PK + k0 + 4 + tig];
                a[mi][3] = s_m[(r+8)*PK + k0 + 4 + tig];
            }
            #pragma unroll
            for (int ni = 0; ni < 4; ni++) {
                int col = cg*32 + ni*8 + gid;
                unsigned b0 = s_B[(k0 + tig)*PB + col];
                unsigned b1 = s_B[(k0 + 4 + tig)*PB + col];
                MMA_TF32(acc[0][ni][0], acc[0][ni][1], acc[0][ni][2], acc[0][ni][3],
                         a[0][0], a[0][1], a[0][2], a[0][3], b0, b1);
                MMA_TF32(acc[1][ni][0], acc[1][ni][1], acc[1][ni][2], acc[1][ni][3],
                         a[1][0], a[1][1], a[1][2], a[1][3], b0, b1);
            }
        }
        #pragma unroll
        for (int mi = 0; mi < 2; mi++)
            #pragma unroll
            for (int ni = 0; ni < 4; ni++)
                #pragma unroll
                for (int q = 0; q < 4; q++)
                    vmax[mi][ni][q] = fmaxf(vmax[mi][ni][q], acc[mi][ni][q]);
        __syncthreads();
    }

    // x = tanh(vmax + b_m2) -> s_m (tf32)
    #pragma unroll
    for (int mi = 0; mi < 2; mi++)
        #pragma unroll
        for (int ni = 0; ni < 4; ni++)
            #pragma unroll
            for (int q = 0; q < 4; q++) {
                int row = rg*32 + mi*16 + gid + ((q >= 2) ? 8 : 0);
                int col = cg*32 + ni*8 + 2*tig + (q & 1);
                float xv = tanha(vmax[mi][ni][q] + b_m2[col]);
                s_m[row*PK + col] = tf32r(xv);
            }
    for (int i = tid; i < 128*32; i += 256) {
        int k2 = i >> 5, c4 = (i & 31) * 4;
        float4 w = *reinterpret_cast<const float4*>(&W_a1[k2*128 + c4]);
        uint4 v = make_uint4(tf32r(w.x), tf32r(w.y), tf32r(w.z), tf32r(w.w));
        *reinterpret_cast<uint4*>(&s_B[k2*PB + c4]) = v;
    }
    __syncthreads();

    // y-GEMM
    float acc[2][4][4];
    #pragma unroll
    for (int mi = 0; mi < 2; mi++)
        #pragma unroll
        for (int ni = 0; ni < 4; ni++)
            #pragma unroll
            for (int q = 0; q < 4; q++) acc[mi][ni][q] = 0.f;
    #pragma unroll
    for (int ks = 0; ks < 16; ks++) {
        int k0 = ks * 8;
        unsigned a[2][4];
        #pragma unroll
        for (int mi = 0; mi < 2; mi++) {
            int r = rg*32 + mi*16 + gid;
            a[mi][0] = s_m[r*PK + k0 + tig];
            a[mi][1] = s_m[(r+8)*PK + k0 + tig];
            a[mi][2] = s_m[r*PK + k0 + 4 + tig];
            a[mi][3] = s_m[(r+8)*PK + k0 + 4 + tig];
        }
        #pragma unroll
        for (int ni = 0; ni < 4; ni++) {
            int col = cg*32 + ni*8 + gid;
            unsigned b0 = s_B[(k0 + tig)*PB + col];
            unsigned b1 = s_B[(k0 + 4 + tig)*PB + col];
            MMA_TF32(acc[0][ni][0], acc[0][ni][1], acc[0][ni][2], acc[0][ni][3],
                     a[0][0], a[0][1], a[0][2], a[0][3], b0, b1);
            MMA_TF32(acc[1][ni][0], acc[1][ni][1], acc[1][ni][2], acc[1][ni][3],
                     a[1][0], a[1][1], a[1][2], a[1][3], b0, b1);
        }
    }
    __syncthreads();

    float* s_y = (float*)s_m;
    #pragma unroll
    for (int mi = 0; mi < 2; mi++)
        #pragma unroll
        for (int ni = 0; ni < 4; ni++)
            #pragma unroll
            for (int q = 0; q < 4; q++) {
                int row = rg*32 + mi*16 + gid + ((q >= 2) ? 8 : 0);
                int col = cg*32 + ni*8 + 2*tig + (q & 1);
                s_y[row*PK + col] = tanha(acc[mi][ni][q] + b_a1[col]);
            }
    __syncthreads();

    {
        int r = tid >> 2, o = tid & 3;
        float s = b_a2[o];
        #pragma unroll 4
        for (int kk = 0; kk < 128; kk++) s += s_y[r*PK + kk] * W_a2[kk*4 + o];
        int row = row0 + r;
        int b = row / NB, n = row - b*NB;
        if (o < 2) {
            float tv = tar[row*2 + o];
            out[b*60 + 2*n + o] = 0.3f*tanhf(s) + 0.3f*tanhf(tv);
        } else {
            float t = tanhf(s);
            out[BSZ*60 + b*60 + 2*n + (o-2)] = expf(3.5f*t - 1.5f);
        }
    }
}

// ---------------- launch ----------------
extern "C" void kernel_launch(void* const* d_in, const int* in_sizes, int n_in,
                              void* d_out, int out_size)
{
    const float* state_inp = (const float*)d_in[0];
    const float* tar       = (const float*)d_in[1];
    const float* W_in1     = (const float*)d_in[2];
    const float* b_in1     = (const float*)d_in[3];
    const float* W_in2     = (const float*)d_in[4];
    const float* b_in2     = (const float*)d_in[5];
    const float* emb_tab   = (const float*)d_in[6];
    const float* W_emb     = (const float*)d_in[7];
    const float* b_emb     = (const float*)d_in[8];
    const float* W_m1      = (const float*)d_in[9];
    const float* b_m1      = (const float*)d_in[10];
    const float* W_m2      = (const float*)d_in[11];
    const float* b_m2      = (const float*)d_in[12];
    const float* W_a1      = (const float*)d_in[13];
    const float* b_a1      = (const float*)d_in[14];
    const float* W_a2      = (const float*)d_in[15];
    const float* b_a2      = (const float*)d_in[16];
    float* out = (float*)d_out;

    cudaFuncSetAttribute(k_feat, cudaFuncAttributeMaxDynamicSharedMemorySize, FK_SMEM);
    cudaFuncSetAttribute(k_msg,  cudaFuncAttributeMaxDynamicSharedMemorySize, SMEM_MSG_BYTES);

    k_setup<<<64, 256>>>(emb_tab, W_emb, b_emb, W_m1);
    k_knn<<<BSZ, 32>>>(state_inp);
    k_feat<<<NROWS/F2R, 512, FK_SMEM>>>(state_inp, tar, W_in1, b_in1, W_in2, b_in2, b_m1);
    k_msg<<<NROWS/RMSG, 256, SMEM_MSG_BYTES>>>(tar, W_m2, b_m2, W_a1, b_a1, W_a2, b_a2, out);
}

// round 16
// speedup vs baseline: 1.1161x; 1.0983x over previous
#include <cuda_runtime.h>
#include <math.h>

#define BSZ   1024
#define NB    30
#define KNN   10
#define HID   128
#define EMB   64
#define NROWS (BSZ*NB)
#define RMSG  64          // rows per k_msg block
#define PK    132         // operand pitch: bank-conflict-free A frags
#define PB    136         // weight pitch : bank-conflict-free B frags

typedef unsigned long long u64;

__device__ __forceinline__ float tanha(float x) {
    float y; asm("tanh.approx.f32 %0, %1;" : "=f"(y) : "f"(x)); return y;
}
__device__ __forceinline__ unsigned tf32r(float x) {
    unsigned r; asm("cvt.rna.tf32.f32 %0, %1;" : "=r"(r) : "f"(x)); return r;
}

#define MMA_TF32(d0,d1,d2,d3,a0,a1,a2,a3,b0,b1) \
    asm volatile("mma.sync.aligned.m16n8k8.row.col.f32.tf32.tf32.f32 " \
        "{%0,%1,%2,%3},{%4,%5,%6,%7},{%8,%9},{%0,%1,%2,%3};" \
        : "+f"(d0),"+f"(d1),"+f"(d2),"+f"(d3) \
        : "r"(a0),"r"(a1),"r"(a2),"r"(a3),"r"(b0),"r"(b1))

// ---------------- device scratch ----------------
__device__ float g_cf[NB*EMB];
__device__ float g_Wcomb[192*256];
__device__ int   g_nbr[NROWS*KNN];
__device__ float g_A[NROWS*HID];
__device__ float g_C[NROWS*HID];

// ---------------- kernel 0: fused precompute + KNN ----------------
// blocks [0,64): setup (cf, Wcomb).  blocks [64,192): KNN, 8 batches per block.
__global__ void k_pre(const float* __restrict__ emb_tab,
                      const float* __restrict__ W_emb,
                      const float* __restrict__ b_emb,
                      const float* __restrict__ W_m1,
                      const float* __restrict__ state_inp)
{
    if (blockIdx.x < 64) {
        int tid = blockIdx.x * 256 + threadIdx.x;
        int stride = 64 * 256;
        for (int idx = tid; idx < NB*EMB; idx += stride) {
            int n = idx / EMB, e = idx - n*EMB;
            int cat = n / (NB/3);
            float s = b_emb[e];
            for (int k = 0; k < EMB; k++)
                s += tanhf(emb_tab[cat*EMB + k]) * W_emb[k*EMB + e];
            g_cf[idx] = tanhf(s);
        }
        for (int idx = tid; idx < 192*256; idx += stride) {
            int k = idx >> 8, c = idx & 255;
            float v;
            if (c < 128) v = W_m1[k*128 + c] - W_m1[(192+k)*128 + c];
            else         v = W_m1[(192+k)*128 + (c-128)];
            g_Wcomb[idx] = v;
        }
    } else {
        // KNN: each warp handles one batch
        __shared__ float px[8][NB], py[8][NB];
        int sub = threadIdx.x >> 5;          // 0..7
        int t   = threadIdx.x & 31;
        int b   = (blockIdx.x - 64) * 8 + sub;
        if (t < NB) {
            px[sub][t] = state_inp[b*60 + 2*t];
            py[sub][t] = state_inp[b*60 + 2*t + 1];
        }
        __syncwarp();
        if (t < NB) {
            float bd[KNN]; int bi[KNN];
            #pragma unroll
            for (int k = 0; k < KNN; k++) { bd[k] = 1e30f; bi[k] = 0; }
            float xi = px[sub][t], yi = py[sub][t];
            for (int j = 0; j < NB; j++) {
                if (j == t) continue;
                float dx = px[sub][j] - xi, dy = py[sub][j] - yi;
                float cd = dx*dx + dy*dy;
                int ci = j;
                #pragma unroll
                for (int k = 0; k < KNN; k++) {
                    if (cd < bd[k]) {
                        float td = bd[k]; int ti = bi[k];
                        bd[k] = cd; bi[k] = ci; cd = td; ci = ti;
                    }
                }
            }
            #pragma unroll
            for (int k = 0; k < KNN; k++) g_nbr[(b*NB + t)*KNN + k] = bi[k];
        }
    }
}

// ---------------- kernel 2: feat MLP + A/C GEMM via mma tf32 (R10: 32 rows, 256 thr, 2 CTA/SM) ----------------
#define FK_PF  196
#define FK_OT  0
#define FK_OF  (32*PK)
#define FK_OB  (FK_OF + 32*FK_PF)
#define FK_SMEM ((FK_OB + 64*PB) * 4)

__global__ __launch_bounds__(256, 2) void k_feat(
    const float* __restrict__ state_inp, const float* __restrict__ tar,
    const float* __restrict__ W_in1, const float* __restrict__ b_in1,
    const float* __restrict__ W_in2, const float* __restrict__ b_in2,
    const float* __restrict__ b_m1)
{
    extern __shared__ float smem[];
    unsigned* s_t = (unsigned*)(smem + FK_OT);
    unsigned* s_f = (unsigned*)(smem + FK_OF);
    unsigned* s_B = (unsigned*)(smem + FK_OB);
    __shared__ float s_in4[32][4];

    const int tid  = threadIdx.x;
    const int wid  = tid >> 5;
    const int lane = tid & 31;
    const int gid  = lane >> 2;
    const int tig  = lane & 3;
    const int row0 = blockIdx.x * 32;

    if (tid < 128) {
        int r = tid >> 2, q = tid & 3;
        int row = row0 + r;
        int b = row / NB, n = row - b*NB;
        float v = (q < 2) ? state_inp[b*60 + 2*n + q] : tanha(tar[row*2 + (q-2)]);
        s_in4[r][q] = v;
    }
    for (int idx = tid; idx < 32*EMB; idx += 256) {
        int r = idx & 31, e = idx >> 5;
        int n = (row0 + r) % NB;
        s_f[r*FK_PF + 128 + e] = tf32r(g_cf[n*EMB + e]);
    }
    __syncthreads();

    {
        const int c  = tid & 127;
        const int rh = tid >> 7;
        float w0 = W_in1[c], w1 = W_in1[128+c], w2 = W_in1[256+c], w3 = W_in1[384+c];
        float bb = b_in1[c];
        #pragma unroll
        for (int m = 0; m < 16; m++) {
            int r = rh*16 + m;
            float4 in = *reinterpret_cast<const float4*>(&s_in4[r][0]);
            s_t[r*PK + c] = tf32r(tanha(bb + w0*in.x + w1*in.y + w2*in.z + w3*in.w));
        }
    }

    {
        float acc[2][2][4];
        #pragma unroll
        for (int mi = 0; mi < 2; mi++)
            #pragma unroll
            for (int ni = 0; ni < 2; ni++)
                #pragma unroll
                for (int q = 0; q < 4; q++) acc[mi][ni][q] = 0.f;

        for (int ch = 0; ch < 2; ch++) {
            __syncthreads();
            for (int i = tid; i < 64*32; i += 256) {
                int kr = i >> 5, c4 = (i & 31) * 4;
                float4 w = *reinterpret_cast<const float4*>(&W_in2[(ch*64 + kr)*128 + c4]);
                uint4 v = make_uint4(tf32r(w.x), tf32r(w.y), tf32r(w.z), tf32r(w.w));
                *reinterpret_cast<uint4*>(&s_B[kr*PB + c4]) = v;
            }
            __syncthreads();
            #pragma unroll
            for (int ks = 0; ks < 8; ks++) {
                int kg = ch*64 + ks*8, k0 = ks*8;
                unsigned a[2][4];
                #pragma unroll
                for (int mi = 0; mi < 2; mi++) {
                    int r = mi*16 + gid;
                    a[mi][0] = s_t[r*PK + kg + tig];
                    a[mi][1] = s_t[(r+8)*PK + kg + tig];
                    a[mi][2] = s_t[r*PK + kg + 4 + tig];
                    a[mi][3] = s_t[(r+8)*PK + kg + 4 + tig];
                }
                #pragma unroll
                for (int ni = 0; ni < 2; ni++) {
                    int col = wid*16 + ni*8 + gid;
                    unsigned b0 = s_B[(k0 + tig)*PB + col];
                    unsigned b1 = s_B[(k0 + 4 + tig)*PB + col];
                    MMA_TF32(acc[0][ni][0], acc[0][ni][1], acc[0][ni][2], acc[0][ni][3],
                             a[0][0], a[0][1], a[0][2], a[0][3], b0, b1);
                    MMA_TF32(acc[1][ni][0], acc[1][ni][1], acc[1][ni][2], acc[1][ni][3],
                             a[1][0], a[1][1], a[1][2], a[1][3], b0, b1);
                }
            }
        }
        #pragma unroll
        for (int mi = 0; mi < 2; mi++)
            #pragma unroll
            for (int ni = 0; ni < 2; ni++)
                #pragma unroll
                for (int q = 0; q < 4; q++) {
                    int row = mi*16 + gid + ((q >= 2) ? 8 : 0);
                    int col = wid*16 + ni*8 + 2*tig + (q & 1);
                    s_f[row*FK_PF + col] = tf32r(tanha(acc[mi][ni][q] + b_in2[col]));
                }
    }

    float* s_stg = (float*)s_t;
    for (int half = 0; half < 2; half++) {
        float acc[2][2][4];
        #pragma unroll
        for (int mi = 0; mi < 2; mi++)
            #pragma unroll
            for (int ni = 0; ni < 2; ni++)
                #pragma unroll
                for (int q = 0; q < 4; q++) acc[mi][ni][q] = 0.f;

        for (int ch = 0; ch < 3; ch++) {
            __syncthreads();
            for (int i = tid; i < 64*32; i += 256) {
                int kr = i >> 5, c4 = (i & 31) * 4;
                float4 w = *reinterpret_cast<const float4*>(&g_Wcomb[(ch*64 + kr)*256 + half*128 + c4]);
                uint4 v = make_uint4(tf32r(w.x), tf32r(w.y), tf32r(w.z), tf32r(w.w));
                *reinterpret_cast<uint4*>(&s_B[kr*PB + c4]) = v;
            }
            __syncthreads();
            #pragma unroll
            for (int ks = 0; ks < 8; ks++) {
                int kg = ch*64 + ks*8, k0 = ks*8;
                unsigned a[2][4];
                #pragma unroll
                for (int mi = 0; mi < 2; mi++) {
                    int r = mi*16 + gid;
                    a[mi][0] = s_f[r*FK_PF + kg + tig];
                    a[mi][1] = s_f[(r+8)*FK_PF + kg + tig];
                    a[mi][2] = s_f[r*FK_PF + kg + 4 + tig];
                    a[mi][3] = s_f[(r+8)*FK_PF + kg + 4 + tig];
                }
                #pragma unroll
                for (int ni = 0; ni < 2; ni++) {
                    int col = wid*16 + ni*8 + gid;
                    unsigned b0 = s_B[(k0 + tig)*PB + col];
                    unsigned b1 = s_B[(k0 + 4 + tig)*PB + col];
                    MMA_TF32(acc[0][ni][0], acc[0][ni][1], acc[0][ni][2], acc[0][ni][3],
                             a[0][0], a[0][1], a[0][2], a[0][3], b0, b1);
                    MMA_TF32(acc[1][ni][0], acc[1][ni][1], acc[1][ni][2], acc[1][ni][3],
                             a[1][0], a[1][1], a[1][2], a[1][3], b0, b1);
                }
            }
        }
        #pragma unroll
        for (int mi = 0; mi < 2; mi++)
            #pragma unroll
            for (int ni = 0; ni < 2; ni++)
                #pragma unroll
                for (int q = 0; q < 4; q++) {
                    int row = mi*16 + gid + ((q >= 2) ? 8 : 0);
                    int col = wid*16 + ni*8 + 2*tig + (q & 1);
                    float v = acc[mi][ni][q] + (half == 0 ? b_m1[col] : 0.0f);
                    s_stg[row*PK + col] = v;
                }
        __syncthreads();
        float* dst = (half == 0) ? g_C : g_A;
        for (int i = tid; i < 32*32; i += 256) {
            int r = i >> 5, c4 = (i & 31) * 4;
            float4 v = *reinterpret_cast<const float4*>(&s_stg[r*PK + c4]);
            *reinterpret_cast<float4*>(&dst[(row0 + r)*128 + c4]) = v;
        }
    }
}

// ---------------- kernel 3: edge msg via mma.sync tf32 (R10: 64 rows, 256 thr, 2 CTA/SM) ----------------
#define OF_M   0                   // s_m: 64 x PK (tf32 operand / y)
#define OF_B   (64*PK)             // s_B: 128 x PB (tf32 weight)
#define OF_NB  (OF_B + 128*PB)
#define SMEM_MSG_BYTES ((OF_NB + RMSG*KNN) * 4)

__global__ __launch_bounds__(256, 2) void k_msg(
    const float* __restrict__ tar,
    const float* __restrict__ W_m2, const float* __restrict__ b_m2,
    const float* __restrict__ W_a1, const float* __restrict__ b_a1,
    const float* __restrict__ W_a2, const float* __restrict__ b_a2,
    float* __restrict__ out)
{
    extern __shared__ float smem[];
    unsigned* s_m  = (unsigned*)(smem + OF_M);
    unsigned* s_B  = (unsigned*)(smem + OF_B);
    int*      s_nb = (int*)(smem + OF_NB);

    const int tid  = threadIdx.x;
    const int wid  = tid >> 5;
    const int lane = tid & 31;
    const int rg   = wid >> 2;
    const int cg   = wid & 3;
    const int gid  = lane >> 2;
    const int tig  = lane & 3;
    const int row0 = blockIdx.x * RMSG;

    for (int i = tid; i < 128*32; i += 256) {
        int k = i >> 5, c4 = (i & 31) * 4;
        float4 w = *reinterpret_cast<const float4*>(&W_m2[k*128 + c4]);
        uint4 v = make_uint4(tf32r(w.x), tf32r(w.y), tf32r(w.z), tf32r(w.w));
        *reinterpret_cast<uint4*>(&s_B[k*PB + c4]) = v;
    }
    for (int idx = tid; idx < RMSG*KNN; idx += 256) {
        int r = idx / KNN;
        int b = (row0 + r) / NB;
        s_nb[idx] = b*NB + g_nbr[row0*KNN + idx];
    }
    __syncthreads();

    float vmax[2][4][4];
    #pragma unroll
    for (int mi = 0; mi < 2; mi++)
        #pragma unroll
        for (int ni = 0; ni < 4; ni++)
            #pragma unroll
            for (int q = 0; q < 4; q++) vmax[mi][ni][q] = -1e30f;

    for (int k = 0; k < KNN; k++) {
        #pragma unroll
        for (int it = 0; it < 8; it++) {
            int p = tid + 256*it;
            int r = p >> 5, j = (p & 31) * 4;
            float4 a = *reinterpret_cast<const float4*>(&g_A[s_nb[r*KNN + k]*128 + j]);
            float4 c = *reinterpret_cast<const float4*>(&g_C[(row0 + r)*128 + j]);
            uint4 v = make_uint4(tf32r(tanha(c.x + a.x)), tf32r(tanha(c.y + a.y)),
                                 tf32r(tanha(c.z + a.z)), tf32r(tanha(c.w + a.w)));
            *reinterpret_cast<uint4*>(&s_m[r*PK + j]) = v;
        }
        __syncthreads();

        float acc[2][4][4];
        #pragma unroll
        for (int mi = 0; mi < 2; mi++)
            #pragma unroll
            for (int ni = 0; ni < 4; ni++)
                #pragma unroll
                for (int q = 0; q < 4; q++) acc[mi][ni][q] = 0.f;

        #pragma unroll
        for (int ks = 0; ks < 16; ks++) {
            int k0 = ks * 8;
            unsigned a[2][4];
            #pragma unroll
            for (int mi = 0; mi < 2; mi++) {
                int r = rg*32 + mi*16 + gid;
                a[mi][0] = s_m[r*PK + k0 + tig];
                a[mi][1] = s_m[(r+8)*PK + k0 + tig];
                a[mi][2] = s_m[r*PK + k0 + 4 + tig];
                a[mi][3] = s_m[(r+8)*PK + k0 + 4 + tig];
            }
            #pragma unroll
            for (int ni = 0; ni < 4; ni++) {
                int col = cg*32 + ni*8 + gid;
                unsigned b0 = s_B[(k0 + tig)*PB + col];
                unsigned b1 = s_B[(k0 + 4 + tig)*PB + col];
                MMA_TF32(acc[0][ni][0], acc[0][ni][1], acc[0][ni][2], acc[0][ni][3],
                         a[0][0], a[0][1], a[0][2], a[0][3], b0, b1);
                MMA_TF32(acc[1][ni][0], acc[1][ni][1], acc[1][ni][2], acc[1][ni][3],
                         a[1][0], a[1][1], a[1][2], a[1][3], b0, b1);
            }
        }
        #pragma unroll
        for (int mi = 0; mi < 2; mi++)
            #pragma unroll
            for (int ni = 0; ni < 4; ni++)
                #pragma unroll
                for (int q = 0; q < 4; q++)
                    vmax[mi][ni][q] = fmaxf(vmax[mi][ni][q], acc[mi][ni][q]);
        __syncthreads();
    }

    // x = tanh(vmax + b_m2) -> s_m (tf32)
    #pragma unroll
    for (int mi = 0; mi < 2; mi++)
        #pragma unroll
        for (int ni = 0; ni < 4; ni++)
            #pragma unroll
            for (int q = 0; q < 4; q++) {
                int row = rg*32 + mi*16 + gid + ((q >= 2) ? 8 : 0);
                int col = cg*32 + ni*8 + 2*tig + (q & 1);
                float xv = tanha(vmax[mi][ni][q] + b_m2[col]);
                s_m[row*PK + col] = tf32r(xv);
            }
    for (int i = tid; i < 128*32; i += 256) {
        int k2 = i >> 5, c4 = (i & 31) * 4;
        float4 w = *reinterpret_cast<const float4*>(&W_a1[k2*128 + c4]);
        uint4 v = make_uint4(tf32r(w.x), tf32r(w.y), tf32r(w.z), tf32r(w.w));
        *reinterpret_cast<uint4*>(&s_B[k2*PB + c4]) = v;
    }
    __syncthreads();

    // y-GEMM
    float acc[2][4][4];
    #pragma unroll
    for (int mi = 0; mi < 2; mi++)
        #pragma unroll
        for (int ni = 0; ni < 4; ni++)
            #pragma unroll
            for (int q = 0; q < 4; q++) acc[mi][ni][q] = 0.f;
    #pragma unroll
    for (int ks = 0; ks < 16; ks++) {
        int k0 = ks * 8;
        unsigned a[2][4];
        #pragma unroll
        for (int mi = 0; mi < 2; mi++) {
            int r = rg*32 + mi*16 + gid;
            a[mi][0] = s_m[r*PK + k0 + tig];
            a[mi][1] = s_m[(r+8)*PK + k0 + tig];
            a[mi][2] = s_m[r*PK + k0 + 4 + tig];
            a[mi][3] = s_m[(r+8)*PK + k0 + 4 + tig];
        }
        #pragma unroll
        for (int ni = 0; ni < 4; ni++) {
            int col = cg*32 + ni*8 + gid;
            unsigned b0 = s_B[(k0 + tig)*PB + col];
            unsigned b1 = s_B[(k0 + 4 + tig)*PB + col];
            MMA_TF32(acc[0][ni][0], acc[0][ni][1], acc[0][ni][2], acc[0][ni][3],
                     a[0][0], a[0][1], a[0][2], a[0][3], b0, b1);
            MMA_TF32(acc[1][ni][0], acc[1][ni][1], acc[1][ni][2], acc[1][ni][3],
                     a[1][0], a[1][1], a[1][2], a[1][3], b0, b1);
        }
    }
    __syncthreads();

    float* s_y = (float*)s_m;
    #pragma unroll
    for (int mi = 0; mi < 2; mi++)
        #pragma unroll
        for (int ni = 0; ni < 4; ni++)
            #pragma unroll
            for (int q = 0; q < 4; q++) {
                int row = rg*32 + mi*16 + gid + ((q >= 2) ? 8 : 0);
                int col = cg*32 + ni*8 + 2*tig + (q & 1);
                s_y[row*PK + col] = tanha(acc[mi][ni][q] + b_a1[col]);
            }
    __syncthreads();

    {
        int r = tid >> 2, o = tid & 3;
        float s = b_a2[o];
        #pragma unroll 4
        for (int kk = 0; kk < 128; kk++) s += s_y[r*PK + kk] * W_a2[kk*4 + o];
        int row = row0 + r;
        int b = row / NB, n = row - b*NB;
        if (o < 2) {
            float tv = tar[row*2 + o];
            out[b*60 + 2*n + o] = 0.3f*tanhf(s) + 0.3f*tanhf(tv);
        } else {
            float t = tanhf(s);
            out[BSZ*60 + b*60 + 2*n + (o-2)] = expf(3.5f*t - 1.5f);
        }
    }
}

// ---------------- launch ----------------
extern "C" void kernel_launch(void* const* d_in, const int* in_sizes, int n_in,
                              void* d_out, int out_size)
{
    const float* state_inp = (const float*)d_in[0];
    const float* tar       = (const float*)d_in[1];
    const float* W_in1     = (const float*)d_in[2];
    const float* b_in1     = (const float*)d_in[3];
    const float* W_in2     = (const float*)d_in[4];
    const float* b_in2     = (const float*)d_in[5];
    const float* emb_tab   = (const float*)d_in[6];
    const float* W_emb     = (const float*)d_in[7];
    const float* b_emb     = (const float*)d_in[8];
    const float* W_m1      = (const float*)d_in[9];
    const float* b_m1      = (const float*)d_in[10];
    const float* W_m2      = (const float*)d_in[11];
    const float* b_m2      = (const float*)d_in[12];
    const float* W_a1      = (const float*)d_in[13];
    const float* b_a1      = (const float*)d_in[14];
    const float* W_a2      = (const float*)d_in[15];
    const float* b_a2      = (const float*)d_in[16];
    float* out = (float*)d_out;

    cudaFuncSetAttribute(k_feat, cudaFuncAttributeMaxDynamicSharedMemorySize, FK_SMEM);
    cudaFuncSetAttribute(k_msg,  cudaFuncAttributeMaxDynamicSharedMemorySize, SMEM_MSG_BYTES);

    k_pre<<<192, 256>>>(emb_tab, W_emb, b_emb, W_m1, state_inp);
    k_feat<<<NROWS/32, 256, FK_SMEM>>>(state_inp, tar, W_in1, b_in1, W_in2, b_in2, b_m1);
    k_msg<<<NROWS/RMSG, 256, SMEM_MSG_BYTES>>>(tar, W_m2, b_m2, W_a1, b_a1, W_a2, b_a2, out);
}

// round 17
// speedup vs baseline: 1.1187x; 1.0023x over previous
#include <cuda_runtime.h>
#include <math.h>

#define BSZ   1024
#define NB    30
#define KNN   10
#define HID   128
#define EMB   64
#define NROWS (BSZ*NB)
#define RMSG  64          // rows per k_msg block
#define PK    132         // operand pitch: bank-conflict-free A frags
#define PB    136         // weight pitch : bank-conflict-free B frags

typedef unsigned long long u64;

__device__ __forceinline__ float tanha(float x) {
    float y; asm("tanh.approx.f32 %0, %1;" : "=f"(y) : "f"(x)); return y;
}
__device__ __forceinline__ unsigned tf32r(float x) {
    unsigned r; asm("cvt.rna.tf32.f32 %0, %1;" : "=r"(r) : "f"(x)); return r;
}

#define MMA_TF32(d0,d1,d2,d3,a0,a1,a2,a3,b0,b1) \
    asm volatile("mma.sync.aligned.m16n8k8.row.col.f32.tf32.tf32.f32 " \
        "{%0,%1,%2,%3},{%4,%5,%6,%7},{%8,%9},{%0,%1,%2,%3};" \
        : "+f"(d0),"+f"(d1),"+f"(d2),"+f"(d3) \
        : "r"(a0),"r"(a1),"r"(a2),"r"(a3),"r"(b0),"r"(b1))

// ---------------- device scratch ----------------
__device__ float g_cf[NB*EMB];
__device__ float g_Wcomb[192*256];
__device__ int   g_nbr[NROWS*KNN];
__device__ float g_A[NROWS*HID];
__device__ float g_C[NROWS*HID];

// ---------------- kernel 0: fused precompute + KNN ----------------
// blocks [0,128): setup (cf, Wcomb).  blocks [128,256): KNN, 8 batches per block.
#define NSETUP 128
__global__ void k_pre(const float* __restrict__ emb_tab,
                      const float* __restrict__ W_emb,
                      const float* __restrict__ b_emb,
                      const float* __restrict__ W_m1,
                      const float* __restrict__ state_inp)
{
    if (blockIdx.x < NSETUP) {
        __shared__ float s_temb[3*EMB];
        if (threadIdx.x < 3*EMB) s_temb[threadIdx.x] = tanha(emb_tab[threadIdx.x]);
        __syncthreads();
        int tid = blockIdx.x * 256 + threadIdx.x;
        int stride = NSETUP * 256;
        for (int idx = tid; idx < NB*EMB; idx += stride) {
            int n = idx / EMB, e = idx - n*EMB;
            int cat = n / (NB/3);
            float s = b_emb[e];
            #pragma unroll 8
            for (int k = 0; k < EMB; k++)
                s += s_temb[cat*EMB + k] * W_emb[k*EMB + e];
            g_cf[idx] = tanha(s);
        }
        for (int idx = tid; idx < 192*256; idx += stride) {
            int k = idx >> 8, c = idx & 255;
            float v;
            if (c < 128) v = W_m1[k*128 + c] - W_m1[(192+k)*128 + c];
            else         v = W_m1[(192+k)*128 + (c-128)];
            g_Wcomb[idx] = v;
        }
    } else {
        // KNN: each warp handles one batch
        __shared__ float px[8][NB], py[8][NB];
        int sub = threadIdx.x >> 5;          // 0..7
        int t   = threadIdx.x & 31;
        int b   = (blockIdx.x - NSETUP) * 8 + sub;
        if (t < NB) {
            px[sub][t] = state_inp[b*60 + 2*t];
            py[sub][t] = state_inp[b*60 + 2*t + 1];
        }
        __syncwarp();
        if (t < NB) {
            float bd[KNN]; int bi[KNN];
            #pragma unroll
            for (int k = 0; k < KNN; k++) { bd[k] = 1e30f; bi[k] = 0; }
            float xi = px[sub][t], yi = py[sub][t];
            for (int j = 0; j < NB; j++) {
                if (j == t) continue;
                float dx = px[sub][j] - xi, dy = py[sub][j] - yi;
                float cd = dx*dx + dy*dy;
                int ci = j;
                #pragma unroll
                for (int k = 0; k < KNN; k++) {
                    if (cd < bd[k]) {
                        float td = bd[k]; int ti = bi[k];
                        bd[k] = cd; bi[k] = ci; cd = td; ci = ti;
                    }
                }
            }
            #pragma unroll
            for (int k = 0; k < KNN; k++) g_nbr[(b*NB + t)*KNN + k] = bi[k];
        }
    }
}

// ---------------- kernel 2: feat MLP + A/C GEMM via mma tf32 (32 rows, 256 thr, 2 CTA/SM) ----------------
#define FK_PF  196
#define FK_OT  0
#define FK_OF  (32*PK)
#define FK_OB  (FK_OF + 32*FK_PF)
#define FK_SMEM ((FK_OB + 64*PB) * 4)

__global__ __launch_bounds__(256, 2) void k_feat(
    const float* __restrict__ state_inp, const float* __restrict__ tar,
    const float* __restrict__ W_in1, const float* __restrict__ b_in1,
    const float* __restrict__ W_in2, const float* __restrict__ b_in2,
    const float* __restrict__ b_m1)
{
    extern __shared__ float smem[];
    unsigned* s_t = (unsigned*)(smem + FK_OT);
    unsigned* s_f = (unsigned*)(smem + FK_OF);
    unsigned* s_B = (unsigned*)(smem + FK_OB);
    __shared__ float s_in4[32][4];

    const int tid  = threadIdx.x;
    const int wid  = tid >> 5;
    const int lane = tid & 31;
    const int gid  = lane >> 2;
    const int tig  = lane & 3;
    const int row0 = blockIdx.x * 32;

    if (tid < 128) {
        int r = tid >> 2, q = tid & 3;
        int row = row0 + r;
        int b = row / NB, n = row - b*NB;
        float v = (q < 2) ? state_inp[b*60 + 2*n + q] : tanha(tar[row*2 + (q-2)]);
        s_in4[r][q] = v;
    }
    for (int idx = tid; idx < 32*EMB; idx += 256) {
        int r = idx & 31, e = idx >> 5;
        int n = (row0 + r) % NB;
        s_f[r*FK_PF + 128 + e] = tf32r(g_cf[n*EMB + e]);
    }
    __syncthreads();

    {
        const int c  = tid & 127;
        const int rh = tid >> 7;
        float w0 = W_in1[c], w1 = W_in1[128+c], w2 = W_in1[256+c], w3 = W_in1[384+c];
        float bb = b_in1[c];
        #pragma unroll
        for (int m = 0; m < 16; m++) {
            int r = rh*16 + m;
            float4 in = *reinterpret_cast<const float4*>(&s_in4[r][0]);
            s_t[r*PK + c] = tf32r(tanha(bb + w0*in.x + w1*in.y + w2*in.z + w3*in.w));
        }
    }

    {
        float acc[2][2][4];
        #pragma unroll
        for (int mi = 0; mi < 2; mi++)
            #pragma unroll
            for (int ni = 0; ni < 2; ni++)
                #pragma unroll
                for (int q = 0; q < 4; q++) acc[mi][ni][q] = 0.f;

        for (int ch = 0; ch < 2; ch++) {
            __syncthreads();
            for (int i = tid; i < 64*32; i += 256) {
                int kr = i >> 5, c4 = (i & 31) * 4;
                float4 w = *reinterpret_cast<const float4*>(&W_in2[(ch*64 + kr)*128 + c4]);
                uint4 v = make_uint4(tf32r(w.x), tf32r(w.y), tf32r(w.z), tf32r(w.w));
                *reinterpret_cast<uint4*>(&s_B[kr*PB + c4]) = v;
            }
            __syncthreads();
            #pragma unroll
            for (int ks = 0; ks < 8; ks++) {
                int kg = ch*64 + ks*8, k0 = ks*8;
                unsigned a[2][4];
                #pragma unroll
                for (int mi = 0; mi < 2; mi++) {
                    int r = mi*16 + gid;
                    a[mi][0] = s_t[r*PK + kg + tig];
                    a[mi][1] = s_t[(r+8)*PK + kg + tig];
                    a[mi][2] = s_t[r*PK + kg + 4 + tig];
                    a[mi][3] = s_t[(r+8)*PK + kg + 4 + tig];
                }
                #pragma unroll
                for (int ni = 0; ni < 2; ni++) {
                    int col = wid*16 + ni*8 + gid;
                    unsigned b0 = s_B[(k0 + tig)*PB + col];
                    unsigned b1 = s_B[(k0 + 4 + tig)*PB + col];
                    MMA_TF32(acc[0][ni][0], acc[0][ni][1], acc[0][ni][2], acc[0][ni][3],
                             a[0][0], a[0][1], a[0][2], a[0][3], b0, b1);
                    MMA_TF32(acc[1][ni][0], acc[1][ni][1], acc[1][ni][2], acc[1][ni][3],
                             a[1][0], a[1][1], a[1][2], a[1][3], b0, b1);
                }
            }
        }
        #pragma unroll
        for (int mi = 0; mi < 2; mi++)
            #pragma unroll
            for (int ni = 0; ni < 2; ni++)
                #pragma unroll
                for (int q = 0; q < 4; q++) {
                    int row = mi*16 + gid + ((q >= 2) ? 8 : 0);
                    int col = wid*16 + ni*8 + 2*tig + (q & 1);
                    s_f[row*FK_PF + col] = tf32r(tanha(acc[mi][ni][q] + b_in2[col]));
                }
    }

    float* s_stg = (float*)s_t;
    for (int half = 0; half < 2; half++) {
        float acc[2][2][4];
        #pragma unroll
        for (int mi = 0; mi < 2; mi++)
            #pragma unroll
            for (int ni = 0; ni < 2; ni++)
                #pragma unroll
                for (int q = 0; q < 4; q++) acc[mi][ni][q] = 0.f;

        for (int ch = 0; ch < 3; ch++) {
            __syncthreads();
            for (int i = tid; i < 64*32; i += 256) {
                int kr = i >> 5, c4 = (i & 31) * 4;
                float4 w = *reinterpret_cast<const float4*>(&g_Wcomb[(ch*64 + kr)*256 + half*128 + c4]);
                uint4 v = make_uint4(tf32r(w.x), tf32r(w.y), tf32r(w.z), tf32r(w.w));
                *reinterpret_cast<uint4*>(&s_B[kr*PB + c4]) = v;
            }
            __syncthreads();
            #pragma unroll
            for (int ks = 0; ks < 8; ks++) {
                int kg = ch*64 + ks*8, k0 = ks*8;
                unsigned a[2][4];
                #pragma unroll
                for (int mi = 0; mi < 2; mi++) {
                    int r = mi*16 + gid;
                    a[mi][0] = s_f[r*FK_PF + kg + tig];
                    a[mi][1] = s_f[(r+8)*FK_PF + kg + tig];
                    a[mi][2] = s_f[r*FK_PF + kg + 4 + tig];
                    a[mi][3] = s_f[(r+8)*FK_PF + kg + 4 + tig];
                }
                #pragma unroll
                for (int ni = 0; ni < 2; ni++) {
                    int col = wid*16 + ni*8 + gid;
                    unsigned b0 = s_B[(k0 + tig)*PB + col];
                    unsigned b1 = s_B[(k0 + 4 + tig)*PB + col];
                    MMA_TF32(acc[0][ni][0], acc[0][ni][1], acc[0][ni][2], acc[0][ni][3],
                             a[0][0], a[0][1], a[0][2], a[0][3], b0, b1);
                    MMA_TF32(acc[1][ni][0], acc[1][ni][1], acc[1][ni][2], acc[1][ni][3],
                             a[1][0], a[1][1], a[1][2], a[1][3], b0, b1);
                }
            }
        }
        #pragma unroll
        for (int mi = 0; mi < 2; mi++)
            #pragma unroll
            for (int ni = 0; ni < 2; ni++)
                #pragma unroll
                for (int q = 0; q < 4; q++) {
                    int row = mi*16 + gid + ((q >= 2) ? 8 : 0);
                    int col = wid*16 + ni*8 + 2*tig + (q & 1);
                    float v = acc[mi][ni][q] + (half == 0 ? b_m1[col] : 0.0f);
                    s_stg[row*PK + col] = v;
                }
        __syncthreads();
        float* dst = (half == 0) ? g_C : g_A;
        for (int i = tid; i < 32*32; i += 256) {
            int r = i >> 5, c4 = (i & 31) * 4;
            float4 v = *reinterpret_cast<const float4*>(&s_stg[r*PK + c4]);
            *reinterpret_cast<float4*>(&dst[(row0 + r)*128 + c4]) = v;
        }
    }
}

// ---------------- kernel 3: edge msg via mma.sync tf32 (64 rows, 256 thr, 2 CTA/SM) ----------------
#define OF_M   0                   // s_m: 64 x PK (tf32 operand / y)
#define OF_B   (64*PK)             // s_B: 128 x PB (tf32 weight)
#define OF_NB  (OF_B + 128*PB)
#define SMEM_MSG_BYTES ((OF_NB + RMSG*KNN) * 4)

__global__ __launch_bounds__(256, 2) void k_msg(
    const float* __restrict__ tar,
    const float* __restrict__ W_m2, const float* __restrict__ b_m2,
    const float* __restrict__ W_a1, const float* __restrict__ b_a1,
    const float* __restrict__ W_a2, const float* __restrict__ b_a2,
    float* __restrict__ out)
{
    extern __shared__ float smem[];
    unsigned* s_m  = (unsigned*)(smem + OF_M);
    unsigned* s_B  = (unsigned*)(smem + OF_B);
    int*      s_nb = (int*)(smem + OF_NB);

    const int tid  = threadIdx.x;
    const int wid  = tid >> 5;
    const int lane = tid & 31;
    const int rg   = wid >> 2;
    const int cg   = wid & 3;
    const int gid  = lane >> 2;
    const int tig  = lane & 3;
    const int row0 = blockIdx.x * RMSG;

    for (int i = tid; i < 128*32; i += 256) {
        int k = i >> 5, c4 = (i & 31) * 4;
        float4 w = *reinterpret_cast<const float4*>(&W_m2[k*128 + c4]);
        uint4 v = make_uint4(tf32r(w.x), tf32r(w.y), tf32r(w.z), tf32r(w.w));
        *reinterpret_cast<uint4*>(&s_B[k*PB + c4]) = v;
    }
    for (int idx = tid; idx < RMSG*KNN; idx += 256) {
        int r = idx / KNN;
        int b = (row0 + r) / NB;
        s_nb[idx] = b*NB + g_nbr[row0*KNN + idx];
    }
    __syncthreads();

    float vmax[2][4][4];
    #pragma unroll
    for (int mi = 0; mi < 2; mi++)
        #pragma unroll
        for (int ni = 0; ni < 4; ni++)
            #pragma unroll
            for (int q = 0; q < 4; q++) vmax[mi][ni][q] = -1e30f;

    for (int k = 0; k < KNN; k++) {
        #pragma unroll
        for (int it = 0; it < 8; it++) {
            int p = tid + 256*it;
            int r = p >> 5, j = (p & 31) * 4;
            float4 a = *reinterpret_cast<const float4*>(&g_A[s_nb[r*KNN + k]*128 + j]);
            float4 c = *reinterpret_cast<const float4*>(&g_C[(row0 + r)*128 + j]);
            uint4 v = make_uint4(tf32r(tanha(c.x + a.x)), tf32r(tanha(c.y + a.y)),
                                 tf32r(tanha(c.z + a.z)), tf32r(tanha(c.w + a.w)));
            *reinterpret_cast<uint4*>(&s_m[r*PK + j]) = v;
        }
        __syncthreads();

        float acc[2][4][4];
        #pragma unroll
        for (int mi = 0; mi < 2; mi++)
            #pragma unroll
            for (int ni = 0; ni < 4; ni++)
                #pragma unroll
                for (int q = 0; q < 4; q++) acc[mi][ni][q] = 0.f;

        #pragma unroll
        for (int ks = 0; ks < 16; ks++) {
            int k0 = ks * 8;
            unsigned a[2][4];
            #pragma unroll
            for (int mi = 0; mi < 2; mi++) {
                int r = rg*32 + mi*16 + gid;
                a[mi][0] = s_m[r*PK + k0 + tig];
                a[mi][1] = s_m[(r+8)*PK + k0 + tig];
                a[mi][2] = s_m[r*PK + k0 + 4 + tig];
                a[mi][3] = s_m[(r+8)*PK + k0 + 4 + tig];
            }
            #pragma unroll
            for (int ni = 0; ni < 4; ni++) {
                int col = cg*32 + ni*8 + gid;
                unsigned b0 = s_B[(k0 + tig)*PB + col];
                unsigned b1 = s_B[(k0 + 4 + tig)*PB + col];
                MMA_TF32(acc[0][ni][0], acc[0][ni][1], acc[0][ni][2], acc[0][ni][3],
                         a[0][0], a[0][1], a[0][2], a[0][3], b0, b1);
                MMA_TF32(acc[1][ni][0], acc[1][ni][1], acc[1][ni][2], acc[1][ni][3],
                         a[1][0], a[1][1], a[1][2], a[1][3], b0, b1);
            }
        }
        #pragma unroll
        for (int mi = 0; mi < 2; mi++)
            #pragma unroll
            for (int ni = 0; ni < 4; ni++)
                #pragma unroll
                for (int q = 0; q < 4; q++)
                    vmax[mi][ni][q] = fmaxf(vmax[mi][ni][q], acc[mi][ni][q]);
        __syncthreads();
    }

    // x = tanh(vmax + b_m2) -> s_m (tf32)
    #pragma unroll
    for (int mi = 0; mi < 2; mi++)
        #pragma unroll
        for (int ni = 0; ni < 4; ni++)
            #pragma unroll
            for (int q = 0; q < 4; q++) {
                int row = rg*32 + mi*16 + gid + ((q >= 2) ? 8 : 0);
                int col = cg*32 + ni*8 + 2*tig + (q & 1);
                float xv = tanha(vmax[mi][ni][q] + b_m2[col]);
                s_m[row*PK + col] = tf32r(xv);
            }
    for (int i = tid; i < 128*32; i += 256) {
        int k2 = i >> 5, c4 = (i & 31) * 4;
        float4 w = *reinterpret_cast<const float4*>(&W_a1[k2*128 + c4]);
        uint4 v = make_uint4(tf32r(w.x), tf32r(w.y), tf32r(w.z), tf32r(w.w));
        *reinterpret_cast<uint4*>(&s_B[k2*PB + c4]) = v;
    }
    __syncthreads();

    // y-GEMM
    float acc[2][4][4];
    #pragma unroll
    for (int mi = 0; mi < 2; mi++)
        #pragma unroll
        for (int ni = 0; ni < 4; ni++)
            #pragma unroll
            for (int q = 0; q < 4; q++) acc[mi][ni][q] = 0.f;
    #pragma unroll
    for (int ks = 0; ks < 16; ks++) {
        int k0 = ks * 8;
        unsigned a[2][4];
        #pragma unroll
        for (int mi = 0; mi < 2; mi++) {
            int r = rg*32 + mi*16 + gid;
            a[mi][0] = s_m[r*PK + k0 + tig];
            a[mi][1] = s_m[(r+8)*PK + k0 + tig];
            a[mi][2] = s_m[r*PK + k0 + 4 + tig];
            a[mi][3] = s_m[(r+8)*PK + k0 + 4 + tig];
        }
        #pragma unroll
        for (int ni = 0; ni < 4; ni++) {
            int col = cg*32 + ni*8 + gid;
            unsigned b0 = s_B[(k0 + tig)*PB + col];
            unsigned b1 = s_B[(k0 + 4 + tig)*PB + col];
            MMA_TF32(acc[0][ni][0], acc[0][ni][1], acc[0][ni][2], acc[0][ni][3],
                     a[0][0], a[0][1], a[0][2], a[0][3], b0, b1);
            MMA_TF32(acc[1][ni][0], acc[1][ni][1], acc[1][ni][2], acc[1][ni][3],
                     a[1][0], a[1][1], a[1][2], a[1][3], b0, b1);
        }
    }
    __syncthreads();

    float* s_y = (float*)s_m;
    #pragma unroll
    for (int mi = 0; mi < 2; mi++)
        #pragma unroll
        for (int ni = 0; ni < 4; ni++)
            #pragma unroll
            for (int q = 0; q < 4; q++) {
                int row = rg*32 + mi*16 + gid + ((q >= 2) ? 8 : 0);
                int col = cg*32 + ni*8 + 2*tig + (q & 1);
                s_y[row*PK + col] = tanha(acc[mi][ni][q] + b_a1[col]);
            }
    __syncthreads();

    {
        int r = tid >> 2, o = tid & 3;
        float s = b_a2[o];
        #pragma unroll 4
        for (int kk = 0; kk < 128; kk++) s += s_y[r*PK + kk] * W_a2[kk*4 + o];
        int row = row0 + r;
        int b = row / NB, n = row - b*NB;
        if (o < 2) {
            float tv = tar[row*2 + o];
            out[b*60 + 2*n + o] = 0.3f*tanhf(s) + 0.3f*tanhf(tv);
        } else {
            float t = tanhf(s);
            out[BSZ*60 + b*60 + 2*n + (o-2)] = expf(3.5f*t - 1.5f);
        }
    }
}

// ---------------- launch ----------------
extern "C" void kernel_launch(void* const* d_in, const int* in_sizes, int n_in,
                              void* d_out, int out_size)
{
    const float* state_inp = (const float*)d_in[0];
    const float* tar       = (const float*)d_in[1];
    const float* W_in1     = (const float*)d_in[2];
    const float* b_in1     = (const float*)d_in[3];
    const float* W_in2     = (const float*)d_in[4];
    const float* b_in2     = (const float*)d_in[5];
    const float* emb_tab   = (const float*)d_in[6];
    const float* W_emb     = (const float*)d_in[7];
    const float* b_emb     = (const float*)d_in[8];
    const float* W_m1      = (const float*)d_in[9];
    const float* b_m1      = (const float*)d_in[10];
    const float* W_m2      = (const float*)d_in[11];
    const float* b_m2      = (const float*)d_in[12];
    const float* W_a1      = (const float*)d_in[13];
    const float* b_a1      = (const float*)d_in[14];
    const float* W_a2      = (const float*)d_in[15];
    const float* b_a2      = (const float*)d_in[16];
    float* out = (float*)d_out;

    cudaFuncSetAttribute(k_feat, cudaFuncAttributeMaxDynamicSharedMemorySize, FK_SMEM);
    cudaFuncSetAttribute(k_msg,  cudaFuncAttributeMaxDynamicSharedMemorySize, SMEM_MSG_BYTES);

    k_pre<<<2*NSETUP, 256>>>(emb_tab, W_emb, b_emb, W_m1, state_inp);
    k_feat<<<NROWS/32, 256, FK_SMEM>>>(state_inp, tar, W_in1, b_in1, W_in2, b_in2, b_m1);
    k_msg<<<NROWS/RMSG, 256, SMEM_MSG_BYTES>>>(tar, W_m2, b_m2, W_a1, b_a1, W_a2, b_a2, out);
}